// round 7
// baseline (speedup 1.0000x reference)
#include <cuda_runtime.h>
#include <cuda_fp16.h>
#include <math.h>
#include <stdint.h>

#define T 1024
#define H 1024
#define FF 2048
#define E 8
#define KSEL 2
#define NSLOT (T * KSEL)   // 2048
#define NK1 (H / 32)       // 32 k-chunks gemm1
#define NK2 (FF / 32)      // 64 k-chunks gemm2

// ---------------- scratch (device globals: allocation-free) ----------------
__device__ int   g_count[E];
__device__ int   g_offset[E];
__device__ int   g_tok[NSLOT];
__device__ float g_scale[NSLOT];
// split-fp16 chunk layout (A-side): per 32-value chunk: 64B hi | 64B lo
__device__ unsigned char g_hs[(size_t)T * H * 4];           // 4MB
__device__ unsigned char g_acts[(size_t)NSLOT * FF * 4];    // 16MB
// plain fp16 (B-side weights)
__device__ __half g_w1h[(size_t)E * 2 * FF * H];            // 67MB
__device__ __half g_w2h[(size_t)E * H * FF];                // 33.5MB

// ---------------- helpers ----------------
__device__ __forceinline__ uint32_t s2u(const void* p) {
    return (uint32_t)__cvta_generic_to_shared(p);
}
__device__ __forceinline__ void ldsm4(uint32_t (&r)[4], uint32_t addr) {
    asm volatile("ldmatrix.sync.aligned.m8n8.x4.shared.b16 {%0,%1,%2,%3}, [%4];"
                 : "=r"(r[0]), "=r"(r[1]), "=r"(r[2]), "=r"(r[3]) : "r"(addr));
}
__device__ __forceinline__ void ldsm2(uint32_t (&r)[2], uint32_t addr) {
    asm volatile("ldmatrix.sync.aligned.m8n8.x2.shared.b16 {%0,%1}, [%2];"
                 : "=r"(r[0]), "=r"(r[1]) : "r"(addr));
}
__device__ __forceinline__ void mma16816(float (&c)[4], const uint32_t (&a)[4],
                                         const uint32_t (&b)[2]) {
    asm volatile(
        "mma.sync.aligned.m16n8k16.row.col.f32.f16.f16.f32 "
        "{%0,%1,%2,%3},{%4,%5,%6,%7},{%8,%9},{%0,%1,%2,%3};"
        : "+f"(c[0]), "+f"(c[1]), "+f"(c[2]), "+f"(c[3])
        : "r"(a[0]), "r"(a[1]), "r"(a[2]), "r"(a[3]), "r"(b[0]), "r"(b[1]));
}
__device__ __forceinline__ void cpa16(uint32_t dst, const void* src) {
    asm volatile("cp.async.cg.shared.global [%0], [%1], 16;" :: "r"(dst), "l"(src));
}
#define CP_COMMIT() asm volatile("cp.async.commit_group;" ::: "memory")
#define CP_WAIT1()  asm volatile("cp.async.wait_group 1;" ::: "memory")
#define CP_WAIT0()  asm volatile("cp.async.wait_group 0;" ::: "memory")

// split 2 floats -> hi fp16 pair + lo (residual) fp16 pair
__device__ __forceinline__ void split2h(float x0, float x1, uint32_t& h, uint32_t& l) {
    __half h0 = __float2half_rn(x0);
    __half h1 = __float2half_rn(x1);
    __half l0 = __float2half_rn(x0 - __half2float(h0));
    __half l1 = __float2half_rn(x1 - __half2float(h1));
    h = (uint32_t)__half_as_ushort(h0) | ((uint32_t)__half_as_ushort(h1) << 16);
    l = (uint32_t)__half_as_ushort(l0) | ((uint32_t)__half_as_ushort(l1) << 16);
}

#define ROW_A 144   // 128B data (hi64|lo64) + 16B pad
#define ROW_B 80    // 64B data + 16B pad

// ---------------- routing ----------------
__global__ void route_kernel(const int* __restrict__ sel,
                             const float* __restrict__ scales) {
    __shared__ int s_cnt[E], s_off[E], s_cur[E];
    int tid = threadIdx.x;
    if (tid < E) { s_cnt[tid] = 0; s_cur[tid] = 0; }
    __syncthreads();
    for (int i = tid; i < NSLOT; i += blockDim.x)
        atomicAdd(&s_cnt[sel[i]], 1);
    __syncthreads();
    if (tid == 0) {
        int acc = 0;
        for (int e = 0; e < E; e++) { s_off[e] = acc; acc += s_cnt[e]; }
    }
    __syncthreads();
    if (tid < E) { g_count[tid] = s_cnt[tid]; g_offset[tid] = s_off[tid]; }
    for (int i = tid; i < NSLOT; i += blockDim.x) {
        int e = sel[i];
        int pos = s_off[e] + atomicAdd(&s_cur[e], 1);
        g_tok[pos]   = i / KSEL;
        g_scale[pos] = scales[i];
    }
}

// ---------------- prep: fp32 -> plain fp16 ---------------------------------
__global__ void tofp16(const float* __restrict__ src, __half* __restrict__ dst,
                       int n4) {
    int i4 = blockIdx.x * blockDim.x + threadIdx.x;
    if (i4 >= n4) return;
    float4 v = ((const float4*)src)[i4];
    __half2 a = __floats2half2_rn(v.x, v.y);
    __half2 b = __floats2half2_rn(v.z, v.w);
    ((uint2*)dst)[i4] = make_uint2(*(uint32_t*)&a, *(uint32_t*)&b);
}

// ---------------- prep: fp32 -> split fp16 chunk layout --------------------
__global__ void split_chunks(const float* __restrict__ src,
                             unsigned char* __restrict__ dst, int n4) {
    int i4 = blockIdx.x * blockDim.x + threadIdx.x;
    if (i4 >= n4) return;
    const int i = i4 * 4;
    float4 v = ((const float4*)src)[i4];
    uint32_t h0, l0, h1, l1;
    split2h(v.x, v.y, h0, l0);
    split2h(v.z, v.w, h1, l1);
    unsigned char* base = dst + (size_t)(i >> 5) * 128 + (i & 31) * 2;
    *(uint2*)base        = make_uint2(h0, h1);
    *(uint2*)(base + 64) = make_uint2(l0, l1);
}

// ---------------- GEMM1: act = silu(X*W1g+b) * (X*W1l+b) -------------------
// CTA: M=128, Ngate=64, Nlin=64, k-chunk=32. (Ah+Al)xBh exact A, fp16 B.
// 3-stage cp.async pipeline, 1 sync per k-iter.
#define G1_BOFF (128 * ROW_A)              // 18432
#define G1_STG  (G1_BOFF + 128 * ROW_B)    // 28672 per stage

__global__ __launch_bounds__(256, 1)
void gemm1_kernel(const float* __restrict__ b1) {
    const int e   = blockIdx.y;
    const int cnt = g_count[e];
    const int m0  = blockIdx.z * 128;
    if (m0 >= cnt) return;
    const int n0  = blockIdx.x * 64;
    const int off = g_offset[e];

    extern __shared__ char sm[];
    __shared__ float s_bg[64], s_bl[64];

    const int tid = threadIdx.x, lane = tid & 31, wid = tid >> 5;
    const int wm = wid & 1, wn = wid >> 1;

    if (tid < 64)       s_bg[tid]      = b1[(size_t)e * 2 * FF + n0 + tid];
    else if (tid < 128) s_bl[tid - 64] = b1[(size_t)e * 2 * FF + FF + n0 + tid - 64];

    // A staging: 128 rows x 128B; 2 thr/row x 64B (4x cp.async 16B)
    const int arow = tid >> 1, ahalf = (tid & 1) * 64;
    const int mrow = m0 + arow;
    const int slot = off + (mrow < cnt ? mrow : cnt - 1);
    const unsigned char* srcA = g_hs + (size_t)g_tok[slot] * (H * 4) + ahalf;
    const uint32_t dA = s2u(sm) + (uint32_t)arow * ROW_A + ahalf;

    // B staging: 128 rows (64 gate + 64 lin) x 64B; 2 thr/row x 32B
    const int brow = tid >> 1, bhalf = (tid & 1) * 32;
    const int bchan = (brow < 64) ? (e * 2 * FF + n0 + brow)
                                  : (e * 2 * FF + FF + n0 + (brow - 64));
    const unsigned char* srcB = (const unsigned char*)(g_w1h + (size_t)bchan * H) + bhalf;
    const uint32_t dB = s2u(sm) + G1_BOFF + (uint32_t)brow * ROW_B + bhalf;

    // ldmatrix bases
    const uint32_t smb = s2u(sm);
    const uint32_t laA = (uint32_t)((lane & 15) + wm * 64) * ROW_A + (lane >> 4) * 16;
    const uint32_t lbB = G1_BOFF + (uint32_t)(wn * 16 + (lane & 7)) * ROW_B +
                         ((lane >> 3) & 1) * 16;

    float cg[4][2][4] = {}, cl[4][2][4] = {};

    // prologue: stages 0, 1
#pragma unroll
    for (int s = 0; s < 2; s++) {
        const uint32_t db = (uint32_t)s * G1_STG;
        const unsigned char* sa = srcA + (size_t)s * 128;
        const unsigned char* sb = srcB + (size_t)s * 64;
#pragma unroll
        for (int q = 0; q < 4; q++) cpa16(dA + db + q * 16, sa + q * 16);
#pragma unroll
        for (int q = 0; q < 2; q++) cpa16(dB + db + q * 16, sb + q * 16);
        CP_COMMIT();
    }

    int buf = 0;
    for (int kt = 0; kt < NK1; kt++) {
        if (kt + 2 < NK1) CP_WAIT1(); else CP_WAIT0();
        __syncthreads();

        // issue stage kt+2 into the buffer freed by compute(kt-1)
        if (kt + 2 < NK1) {
            const int s = kt + 2;
            int nb = buf + 2; if (nb >= 3) nb -= 3;
            const uint32_t db = (uint32_t)nb * G1_STG;
            const unsigned char* sa = srcA + (size_t)s * 128;
            const unsigned char* sb = srcB + (size_t)s * 64;
#pragma unroll
            for (int q = 0; q < 4; q++) cpa16(dA + db + q * 16, sa + q * 16);
#pragma unroll
            for (int q = 0; q < 2; q++) cpa16(dB + db + q * 16, sb + q * 16);
            CP_COMMIT();
        }

        const uint32_t bbu = smb + (uint32_t)buf * G1_STG;
#pragma unroll
        for (int kk = 0; kk < 2; kk++) {
            uint32_t ah[4][4], al[4][4];
#pragma unroll
            for (int i = 0; i < 4; i++) {
                const uint32_t a0 = bbu + laA + i * (16 * ROW_A) + kk * 32;
                ldsm4(ah[i], a0);
                ldsm4(al[i], a0 + 64);
            }
#pragma unroll
            for (int j = 0; j < 2; j++) {
                const uint32_t ba = bbu + lbB + j * (8 * ROW_B) + kk * 32;
                uint32_t bg[2], blin[2];
                ldsm2(bg, ba);
                ldsm2(blin, ba + 64 * ROW_B);
#pragma unroll
                for (int i = 0; i < 4; i++) {
                    mma16816(cg[i][j], ah[i], bg);
                    mma16816(cg[i][j], al[i], bg);
                    mma16816(cl[i][j], ah[i], blin);
                    mma16816(cl[i][j], al[i], blin);
                }
            }
        }
        if (++buf == 3) buf = 0;
    }

    // epilogue: bias + silu(gate)*lin; store act as split fp16 chunks
#pragma unroll
    for (int i = 0; i < 4; i++)
#pragma unroll
        for (int rr = 0; rr < 2; rr++) {
            const int m = wm * 64 + i * 16 + (lane >> 2) + rr * 8 + m0;
            if (m >= cnt) continue;
            unsigned char* actrow = g_acts + (size_t)(off + m) * (FF * 4);
#pragma unroll
            for (int j = 0; j < 2; j++) {
                const int c = wn * 16 + j * 8 + (lane & 3) * 2;
                float r0, r1;
#pragma unroll
                for (int q = 0; q < 2; q++) {
                    const int idx = rr * 2 + q;
                    const float g = cg[i][j][idx] + s_bg[c + q];
                    const float l = cl[i][j][idx] + s_bl[c + q];
                    const float r = g * l / (1.0f + __expf(-g));
                    if (q == 0) r0 = r; else r1 = r;
                }
                uint32_t h, lo;
                split2h(r0, r1, h, lo);
                const int C = n0 + c;
                unsigned char* base = actrow + (size_t)(C >> 5) * 128 + (C & 31) * 2;
                *(uint32_t*)base        = h;
                *(uint32_t*)(base + 64) = lo;
            }
        }
}

// ---------------- GEMM2: out += scale*(act*W2^T + b2) ----------------------
// CTA: M=128, N=64 over H, K=FF. (Ah+Al)xBh. 3-stage cp.async, 1 sync/iter.
#define G2_BOFF (128 * ROW_A)              // 18432
#define G2_STG  (G2_BOFF + 64 * ROW_B)     // 23552 per stage

__global__ __launch_bounds__(256, 1)
void gemm2_kernel(const float* __restrict__ b2, float* __restrict__ out) {
    const int e   = blockIdx.y;
    const int cnt = g_count[e];
    const int m0  = blockIdx.z * 128;
    if (m0 >= cnt) return;
    const int n0  = blockIdx.x * 64;
    const int off = g_offset[e];

    extern __shared__ char sm[];
    __shared__ float s_b2[64];

    const int tid = threadIdx.x, lane = tid & 31, wid = tid >> 5;
    const int wm = wid & 1, wn = wid >> 1;

    if (tid < 64) s_b2[tid] = b2[(size_t)e * H + n0 + tid];

    // A staging: 128 rows x 128B; 2 thr/row x 64B
    const int arow = tid >> 1, ahalf = (tid & 1) * 64;
    const int mrow = m0 + arow;
    const unsigned char* srcA =
        g_acts + (size_t)(off + (mrow < cnt ? mrow : cnt - 1)) * (FF * 4) + ahalf;
    const uint32_t dA = s2u(sm) + (uint32_t)arow * ROW_A + ahalf;

    // B staging: 64 rows x 64B; 4 thr/row x 16B
    const int brow = tid >> 2, boff16 = (tid & 3) * 16;
    const unsigned char* srcB =
        (const unsigned char*)(g_w2h + (size_t)(e * H + n0 + brow) * FF) + boff16;
    const uint32_t dB = s2u(sm) + G2_BOFF + (uint32_t)brow * ROW_B + boff16;

    const uint32_t smb = s2u(sm);
    const uint32_t laA = (uint32_t)((lane & 15) + wm * 64) * ROW_A + (lane >> 4) * 16;
    const uint32_t lbB = G2_BOFF + (uint32_t)(wn * 16 + (lane & 7)) * ROW_B +
                         ((lane >> 3) & 1) * 16;

    float c[4][2][4] = {};

#pragma unroll
    for (int s = 0; s < 2; s++) {
        const uint32_t db = (uint32_t)s * G2_STG;
        const unsigned char* sa = srcA + (size_t)s * 128;
        const unsigned char* sb = srcB + (size_t)s * 64;
#pragma unroll
        for (int q = 0; q < 4; q++) cpa16(dA + db + q * 16, sa + q * 16);
        cpa16(dB + db, sb);
        CP_COMMIT();
    }

    int buf = 0;
    for (int kt = 0; kt < NK2; kt++) {
        if (kt + 2 < NK2) CP_WAIT1(); else CP_WAIT0();
        __syncthreads();

        if (kt + 2 < NK2) {
            const int s = kt + 2;
            int nb = buf + 2; if (nb >= 3) nb -= 3;
            const uint32_t db = (uint32_t)nb * G2_STG;
            const unsigned char* sa = srcA + (size_t)s * 128;
            const unsigned char* sb = srcB + (size_t)s * 64;
#pragma unroll
            for (int q = 0; q < 4; q++) cpa16(dA + db + q * 16, sa + q * 16);
            cpa16(dB + db, sb);
            CP_COMMIT();
        }

        const uint32_t bbu = smb + (uint32_t)buf * G2_STG;
#pragma unroll
        for (int kk = 0; kk < 2; kk++) {
            uint32_t ah[4][4], al[4][4];
#pragma unroll
            for (int i = 0; i < 4; i++) {
                const uint32_t a0 = bbu + laA + i * (16 * ROW_A) + kk * 32;
                ldsm4(ah[i], a0);
                ldsm4(al[i], a0 + 64);
            }
#pragma unroll
            for (int j = 0; j < 2; j++) {
                const uint32_t ba = bbu + lbB + j * (8 * ROW_B) + kk * 32;
                uint32_t bh[2];
                ldsm2(bh, ba);
#pragma unroll
                for (int i = 0; i < 4; i++) {
                    mma16816(c[i][j], ah[i], bh);
                    mma16816(c[i][j], al[i], bh);
                }
            }
        }
        if (++buf == 3) buf = 0;
    }

    // epilogue: scaled atomic scatter
#pragma unroll
    for (int i = 0; i < 4; i++)
#pragma unroll
        for (int rr = 0; rr < 2; rr++) {
            const int m = wm * 64 + i * 16 + (lane >> 2) + rr * 8 + m0;
            if (m >= cnt) continue;
            const int   sl  = off + m;
            const int   tok = g_tok[sl];
            const float sc  = g_scale[sl];
#pragma unroll
            for (int j = 0; j < 2; j++) {
                const int cc = wn * 16 + j * 8 + (lane & 3) * 2;
                atomicAdd(&out[(size_t)tok * H + n0 + cc],
                          sc * (c[i][j][rr * 2 + 0] + s_b2[cc]));
                atomicAdd(&out[(size_t)tok * H + n0 + cc + 1],
                          sc * (c[i][j][rr * 2 + 1] + s_b2[cc + 1]));
            }
        }
}

// ---------------- launch ----------------
extern "C" void kernel_launch(void* const* d_in, const int* in_sizes, int n_in,
                              void* d_out, int out_size) {
    const float* hidden = (const float*)d_in[0];
    const int*   sel    = (const int*)d_in[1];
    const float* scales = (const float*)d_in[2];
    const float* w1     = (const float*)d_in[3];
    const float* b1     = (const float*)d_in[4];
    const float* w2     = (const float*)d_in[5];
    const float* b2     = (const float*)d_in[6];

    void *p_hs, *p_w1h, *p_w2h;
    cudaGetSymbolAddress(&p_hs,  g_hs);
    cudaGetSymbolAddress(&p_w1h, g_w1h);
    cudaGetSymbolAddress(&p_w2h, g_w2h);

    const int smem1 = 3 * G1_STG;   // 86016
    const int smem2 = 3 * G2_STG;   // 70656
    cudaFuncSetAttribute(gemm1_kernel, cudaFuncAttributeMaxDynamicSharedMemorySize, smem1);
    cudaFuncSetAttribute(gemm2_kernel, cudaFuncAttributeMaxDynamicSharedMemorySize, smem2);

    cudaMemsetAsync(d_out, 0, (size_t)T * H * sizeof(float), 0);
    route_kernel<<<1, 256>>>(sel, scales);

    const int n4h  = (T * H) / 4;
    const int n4w1 = (E * 2 * FF * H) / 4;
    const int n4w2 = (E * H * FF) / 4;
    split_chunks<<<(n4h + 255) / 256, 256>>>(hidden, (unsigned char*)p_hs, n4h);
    tofp16<<<(n4w1 + 255) / 256, 256>>>(w1, (__half*)p_w1h, n4w1);
    tofp16<<<(n4w2 + 255) / 256, 256>>>(w2, (__half*)p_w2h, n4w2);

    dim3 g1(FF / 64, E, NSLOT / 128);   // 32 x 8 x 16
    gemm1_kernel<<<g1, 256, smem1>>>(b1);

    dim3 g2(H / 64, E, NSLOT / 128);    // 16 x 8 x 16
    gemm2_kernel<<<g2, 256, smem2>>>(b2, (float*)d_out);
}

// round 8
// speedup vs baseline: 2.0421x; 2.0421x over previous
#include <cuda_runtime.h>
#include <cuda_fp16.h>
#include <math.h>
#include <stdint.h>

#define T 1024
#define H 1024
#define FF 2048
#define E 8
#define KSEL 2
#define NSLOT (T * KSEL)   // 2048
#define NK1 (H / 32)       // 32 k-chunks gemm1
#define NK2 (FF / 32)      // 64 k-chunks gemm2

// ---------------- scratch (device globals: allocation-free) ----------------
__device__ int   g_count[E];
__device__ int   g_offset[E];
__device__ int   g_tok[NSLOT];
__device__ float g_scale[NSLOT];
__device__ __half g_hh[(size_t)T * H];            // 2MB   fp16 hidden
__device__ __half g_acth[(size_t)NSLOT * FF];     // 8MB   fp16 act
__device__ __half g_w1h[(size_t)E * 2 * FF * H];  // 67MB  fp16 w1
__device__ __half g_w2h[(size_t)E * H * FF];      // 33.5MB fp16 w2

// ---------------- helpers ----------------
__device__ __forceinline__ uint32_t s2u(const void* p) {
    return (uint32_t)__cvta_generic_to_shared(p);
}
__device__ __forceinline__ void ldsm4(uint32_t (&r)[4], uint32_t addr) {
    asm volatile("ldmatrix.sync.aligned.m8n8.x4.shared.b16 {%0,%1,%2,%3}, [%4];"
                 : "=r"(r[0]), "=r"(r[1]), "=r"(r[2]), "=r"(r[3]) : "r"(addr));
}
__device__ __forceinline__ void ldsm2(uint32_t (&r)[2], uint32_t addr) {
    asm volatile("ldmatrix.sync.aligned.m8n8.x2.shared.b16 {%0,%1}, [%2];"
                 : "=r"(r[0]), "=r"(r[1]) : "r"(addr));
}
__device__ __forceinline__ void mma16816(float (&c)[4], const uint32_t (&a)[4],
                                         const uint32_t (&b)[2]) {
    asm volatile(
        "mma.sync.aligned.m16n8k16.row.col.f32.f16.f16.f32 "
        "{%0,%1,%2,%3},{%4,%5,%6,%7},{%8,%9},{%0,%1,%2,%3};"
        : "+f"(c[0]), "+f"(c[1]), "+f"(c[2]), "+f"(c[3])
        : "r"(a[0]), "r"(a[1]), "r"(a[2]), "r"(a[3]), "r"(b[0]), "r"(b[1]));
}

#define ROW_S 80    // 64B data (32 fp16) + 16B pad: conflict-free ldmatrix

// ---------------- routing ----------------
__global__ void route_kernel(const int* __restrict__ sel,
                             const float* __restrict__ scales) {
    __shared__ int s_cnt[E], s_off[E], s_cur[E];
    int tid = threadIdx.x;
    if (tid < E) { s_cnt[tid] = 0; s_cur[tid] = 0; }
    __syncthreads();
    for (int i = tid; i < NSLOT; i += blockDim.x)
        atomicAdd(&s_cnt[sel[i]], 1);
    __syncthreads();
    if (tid == 0) {
        int acc = 0;
        for (int e = 0; e < E; e++) { s_off[e] = acc; acc += s_cnt[e]; }
    }
    __syncthreads();
    if (tid < E) { g_count[tid] = s_cnt[tid]; g_offset[tid] = s_off[tid]; }
    for (int i = tid; i < NSLOT; i += blockDim.x) {
        int e = sel[i];
        int pos = s_off[e] + atomicAdd(&s_cur[e], 1);
        g_tok[pos]   = i / KSEL;
        g_scale[pos] = scales[i];
    }
}

// ---------------- prep: fp32 -> fp16 ---------------------------------------
__global__ void tofp16(const float* __restrict__ src, __half* __restrict__ dst,
                       int n4) {
    int i4 = blockIdx.x * blockDim.x + threadIdx.x;
    if (i4 >= n4) return;
    float4 v = ((const float4*)src)[i4];
    __half2 a = __floats2half2_rn(v.x, v.y);
    __half2 b = __floats2half2_rn(v.z, v.w);
    ((uint2*)dst)[i4] = make_uint2(*(uint32_t*)&a, *(uint32_t*)&b);
}

// ---------------- GEMM1: act = silu(X*W1g+b) * (X*W1l+b) -------------------
// CTA: M=128, Ngate=64, Nlin=64, k-chunk=32, plain fp16 single product.
// R6 schedule: LDG->reg->STS double buffer, 2 syncs/iter.
#define G1_BOFF (128 * ROW_S)              // 10240 (A region size)
#define G1_STG  (G1_BOFF + 128 * ROW_S)    // 20480 per stage

__global__ __launch_bounds__(256, 1)
void gemm1_kernel(const float* __restrict__ b1) {
    const int e   = blockIdx.y;
    const int cnt = g_count[e];
    const int m0  = blockIdx.z * 128;
    if (m0 >= cnt) return;
    const int n0  = blockIdx.x * 64;
    const int off = g_offset[e];

    extern __shared__ char sm[];
    __shared__ float s_bg[64], s_bl[64];

    const int tid = threadIdx.x, lane = tid & 31, wid = tid >> 5;
    const int wm = wid & 1, wn = wid >> 1;

    if (tid < 64)       s_bg[tid]      = b1[(size_t)e * 2 * FF + n0 + tid];
    else if (tid < 128) s_bl[tid - 64] = b1[(size_t)e * 2 * FF + FF + n0 + tid - 64];

    // A staging: 128 rows x 64B; 2 thr/row x 32B (2x uint4)
    const int arow = tid >> 1, ahalf = (tid & 1) * 32;
    const int mrow = m0 + arow;
    const int slot = off + (mrow < cnt ? mrow : cnt - 1);
    const unsigned char* srcA =
        (const unsigned char*)(g_hh + (size_t)g_tok[slot] * H) + ahalf;
    const uint32_t dAo = (uint32_t)arow * ROW_S + ahalf;

    // B staging: 128 rows (64 gate + 64 lin) x 64B; 2 thr/row x 32B
    const int brow = tid >> 1, bhalf = (tid & 1) * 32;
    const int bchan = (brow < 64) ? (e * 2 * FF + n0 + brow)
                                  : (e * 2 * FF + FF + n0 + (brow - 64));
    const unsigned char* srcB =
        (const unsigned char*)(g_w1h + (size_t)bchan * H) + bhalf;
    const uint32_t dBo = G1_BOFF + (uint32_t)brow * ROW_S + bhalf;

    // ldmatrix bases
    const uint32_t smb = s2u(sm);
    const uint32_t laA = (uint32_t)((lane & 15) + wm * 64) * ROW_S + (lane >> 4) * 16;
    const uint32_t lbB = G1_BOFF + (uint32_t)(wn * 16 + (lane & 7)) * ROW_S +
                         ((lane >> 3) & 1) * 16;

    float cg[4][2][4] = {}, cl[4][2][4] = {};
    uint4 ra[2], rb[2];

#pragma unroll
    for (int q = 0; q < 2; q++) ra[q] = *(const uint4*)(srcA + q * 16);
#pragma unroll
    for (int q = 0; q < 2; q++) rb[q] = *(const uint4*)(srcB + q * 16);

    for (int kt = 0; kt < NK1; kt++) {
        char* bb = sm + (kt & 1) * G1_STG;
#pragma unroll
        for (int q = 0; q < 2; q++) *(uint4*)(bb + dAo + q * 16) = ra[q];
#pragma unroll
        for (int q = 0; q < 2; q++) *(uint4*)(bb + dBo + q * 16) = rb[q];
        __syncthreads();

        if (kt + 1 < NK1) {
            const unsigned char* sa = srcA + (size_t)(kt + 1) * 64;
            const unsigned char* sb = srcB + (size_t)(kt + 1) * 64;
#pragma unroll
            for (int q = 0; q < 2; q++) ra[q] = *(const uint4*)(sa + q * 16);
#pragma unroll
            for (int q = 0; q < 2; q++) rb[q] = *(const uint4*)(sb + q * 16);
        }

        const uint32_t bbu = smb + (kt & 1) * G1_STG;
#pragma unroll
        for (int kk = 0; kk < 2; kk++) {
            uint32_t ah[4][4];
#pragma unroll
            for (int i = 0; i < 4; i++)
                ldsm4(ah[i], bbu + laA + i * (16 * ROW_S) + kk * 32);
#pragma unroll
            for (int j = 0; j < 2; j++) {
                const uint32_t ba = bbu + lbB + j * (8 * ROW_S) + kk * 32;
                uint32_t bg[2], blin[2];
                ldsm2(bg, ba);
                ldsm2(blin, ba + 64 * ROW_S);
#pragma unroll
                for (int i = 0; i < 4; i++) {
                    mma16816(cg[i][j], ah[i], bg);
                    mma16816(cl[i][j], ah[i], blin);
                }
            }
        }
        __syncthreads();
    }

    // epilogue: bias + silu(gate)*lin; store act as fp16 pairs
#pragma unroll
    for (int i = 0; i < 4; i++)
#pragma unroll
        for (int rr = 0; rr < 2; rr++) {
            const int m = wm * 64 + i * 16 + (lane >> 2) + rr * 8 + m0;
            if (m >= cnt) continue;
            __half* actrow = g_acth + (size_t)(off + m) * FF;
#pragma unroll
            for (int j = 0; j < 2; j++) {
                const int c = wn * 16 + j * 8 + (lane & 3) * 2;
                float r0, r1;
#pragma unroll
                for (int q = 0; q < 2; q++) {
                    const int idx = rr * 2 + q;
                    const float g = cg[i][j][idx] + s_bg[c + q];
                    const float l = cl[i][j][idx] + s_bl[c + q];
                    const float r = g * l / (1.0f + __expf(-g));
                    if (q == 0) r0 = r; else r1 = r;
                }
                __half2 hv = __floats2half2_rn(r0, r1);
                *(uint32_t*)(actrow + n0 + c) = *(uint32_t*)&hv;
            }
        }
}

// ---------------- GEMM2: out += scale*(act*W2^T + b2) ----------------------
// CTA: M=128, N=64 over H, K=FF, plain fp16 single product.
#define G2_BOFF (128 * ROW_S)              // 10240
#define G2_STG  (G2_BOFF + 64 * ROW_S)     // 15360 per stage

__global__ __launch_bounds__(256, 1)
void gemm2_kernel(const float* __restrict__ b2, float* __restrict__ out) {
    const int e   = blockIdx.y;
    const int cnt = g_count[e];
    const int m0  = blockIdx.z * 128;
    if (m0 >= cnt) return;
    const int n0  = blockIdx.x * 64;
    const int off = g_offset[e];

    extern __shared__ char sm[];
    __shared__ float s_b2[64];

    const int tid = threadIdx.x, lane = tid & 31, wid = tid >> 5;
    const int wm = wid & 1, wn = wid >> 1;

    if (tid < 64) s_b2[tid] = b2[(size_t)e * H + n0 + tid];

    // A staging: 128 rows x 64B; 2 thr/row x 32B
    const int arow = tid >> 1, ahalf = (tid & 1) * 32;
    const int mrow = m0 + arow;
    const unsigned char* srcA =
        (const unsigned char*)(g_acth +
            (size_t)(off + (mrow < cnt ? mrow : cnt - 1)) * FF) + ahalf;
    const uint32_t dAo = (uint32_t)arow * ROW_S + ahalf;

    // B staging: 64 rows x 64B; 4 thr/row x 16B
    const int brow = tid >> 2, boff16 = (tid & 3) * 16;
    const unsigned char* srcB =
        (const unsigned char*)(g_w2h + (size_t)(e * H + n0 + brow) * FF) + boff16;
    const uint32_t dBo = G2_BOFF + (uint32_t)brow * ROW_S + boff16;

    const uint32_t smb = s2u(sm);
    const uint32_t laA = (uint32_t)((lane & 15) + wm * 64) * ROW_S + (lane >> 4) * 16;
    const uint32_t lbB = G2_BOFF + (uint32_t)(wn * 16 + (lane & 7)) * ROW_S +
                         ((lane >> 3) & 1) * 16;

    float c[4][2][4] = {};
    uint4 ra[2], rb;

#pragma unroll
    for (int q = 0; q < 2; q++) ra[q] = *(const uint4*)(srcA + q * 16);
    rb = *(const uint4*)srcB;

    for (int kt = 0; kt < NK2; kt++) {
        char* bb = sm + (kt & 1) * G2_STG;
#pragma unroll
        for (int q = 0; q < 2; q++) *(uint4*)(bb + dAo + q * 16) = ra[q];
        *(uint4*)(bb + dBo) = rb;
        __syncthreads();

        if (kt + 1 < NK2) {
            const unsigned char* sa = srcA + (size_t)(kt + 1) * 64;
            const unsigned char* sb = srcB + (size_t)(kt + 1) * 64;
#pragma unroll
            for (int q = 0; q < 2; q++) ra[q] = *(const uint4*)(sa + q * 16);
            rb = *(const uint4*)sb;
        }

        const uint32_t bbu = smb + (kt & 1) * G2_STG;
#pragma unroll
        for (int kk = 0; kk < 2; kk++) {
            uint32_t ah[4][4];
#pragma unroll
            for (int i = 0; i < 4; i++)
                ldsm4(ah[i], bbu + laA + i * (16 * ROW_S) + kk * 32);
#pragma unroll
            for (int j = 0; j < 2; j++) {
                uint32_t bh[2];
                ldsm2(bh, bbu + lbB + j * (8 * ROW_S) + kk * 32);
#pragma unroll
                for (int i = 0; i < 4; i++)
                    mma16816(c[i][j], ah[i], bh);
            }
        }
        __syncthreads();
    }

    // epilogue: scaled atomic scatter
#pragma unroll
    for (int i = 0; i < 4; i++)
#pragma unroll
        for (int rr = 0; rr < 2; rr++) {
            const int m = wm * 64 + i * 16 + (lane >> 2) + rr * 8 + m0;
            if (m >= cnt) continue;
            const int   sl  = off + m;
            const int   tok = g_tok[sl];
            const float sc  = g_scale[sl];
#pragma unroll
            for (int j = 0; j < 2; j++) {
                const int cc = wn * 16 + j * 8 + (lane & 3) * 2;
                atomicAdd(&out[(size_t)tok * H + n0 + cc],
                          sc * (c[i][j][rr * 2 + 0] + s_b2[cc]));
                atomicAdd(&out[(size_t)tok * H + n0 + cc + 1],
                          sc * (c[i][j][rr * 2 + 1] + s_b2[cc + 1]));
            }
        }
}

// ---------------- launch ----------------
extern "C" void kernel_launch(void* const* d_in, const int* in_sizes, int n_in,
                              void* d_out, int out_size) {
    const float* hidden = (const float*)d_in[0];
    const int*   sel    = (const int*)d_in[1];
    const float* scales = (const float*)d_in[2];
    const float* w1     = (const float*)d_in[3];
    const float* b1     = (const float*)d_in[4];
    const float* w2     = (const float*)d_in[5];
    const float* b2     = (const float*)d_in[6];

    void *p_hh, *p_w1h, *p_w2h;
    cudaGetSymbolAddress(&p_hh,  g_hh);
    cudaGetSymbolAddress(&p_w1h, g_w1h);
    cudaGetSymbolAddress(&p_w2h, g_w2h);

    const int smem1 = 2 * G1_STG;   // 40960
    const int smem2 = 2 * G2_STG;   // 30720
    cudaFuncSetAttribute(gemm1_kernel, cudaFuncAttributeMaxDynamicSharedMemorySize, smem1);
    cudaFuncSetAttribute(gemm2_kernel, cudaFuncAttributeMaxDynamicSharedMemorySize, smem2);

    cudaMemsetAsync(d_out, 0, (size_t)T * H * sizeof(float), 0);
    route_kernel<<<1, 256>>>(sel, scales);

    const int n4h  = (T * H) / 4;
    const int n4w1 = (E * 2 * FF * H) / 4;
    const int n4w2 = (E * H * FF) / 4;
    tofp16<<<(n4h  + 255) / 256, 256>>>(hidden, (__half*)p_hh,  n4h);
    tofp16<<<(n4w1 + 255) / 256, 256>>>(w1,     (__half*)p_w1h, n4w1);
    tofp16<<<(n4w2 + 255) / 256, 256>>>(w2,     (__half*)p_w2h, n4w2);

    dim3 g1(FF / 64, E, NSLOT / 128);   // 32 x 8 x 16
    gemm1_kernel<<<g1, 256, smem1>>>(b1);

    dim3 g2(H / 64, E, NSLOT / 128);    // 16 x 8 x 16
    gemm2_kernel<<<g2, 256, smem2>>>(b2, (float*)d_out);
}

// round 9
// speedup vs baseline: 2.3779x; 1.1645x over previous
#include <cuda_runtime.h>
#include <cuda_fp16.h>
#include <math.h>
#include <stdint.h>

#define T 1024
#define H 1024
#define FF 2048
#define E 8
#define KSEL 2
#define NSLOT (T * KSEL)   // 2048
#define NK1 (H / 64)       // 16 k-chunks gemm1
#define NK2 (FF / 64)      // 32 k-chunks gemm2

// ---------------- scratch (device globals: allocation-free) ----------------
__device__ int   g_count[E];
__device__ int   g_offset[E];
__device__ int   g_tok[NSLOT];
__device__ float g_scale[NSLOT];
__device__ __half g_hh[(size_t)T * H];            // 2MB   fp16 hidden
__device__ __half g_acth[(size_t)NSLOT * FF];     // 8MB   fp16 act
__device__ __half g_w1h[(size_t)E * 2 * FF * H];  // 67MB  fp16 w1
__device__ __half g_w2h[(size_t)E * H * FF];      // 33.5MB fp16 w2

// ---------------- helpers ----------------
__device__ __forceinline__ uint32_t s2u(const void* p) {
    return (uint32_t)__cvta_generic_to_shared(p);
}
__device__ __forceinline__ void ldsm4(uint32_t (&r)[4], uint32_t addr) {
    asm volatile("ldmatrix.sync.aligned.m8n8.x4.shared.b16 {%0,%1,%2,%3}, [%4];"
                 : "=r"(r[0]), "=r"(r[1]), "=r"(r[2]), "=r"(r[3]) : "r"(addr));
}
__device__ __forceinline__ void mma16816(float (&c)[4], const uint32_t (&a)[4],
                                         const uint32_t* b) {
    asm volatile(
        "mma.sync.aligned.m16n8k16.row.col.f32.f16.f16.f32 "
        "{%0,%1,%2,%3},{%4,%5,%6,%7},{%8,%9},{%0,%1,%2,%3};"
        : "+f"(c[0]), "+f"(c[1]), "+f"(c[2]), "+f"(c[3])
        : "r"(a[0]), "r"(a[1]), "r"(a[2]), "r"(a[3]), "r"(b[0]), "r"(b[1]));
}

#define ROW_S 144   // 128B data (64 fp16) + 16B pad: conflict-free ldmatrix

// ---------------- routing ----------------
__global__ void route_kernel(const int* __restrict__ sel,
                             const float* __restrict__ scales) {
    __shared__ int s_cnt[E], s_off[E], s_cur[E];
    int tid = threadIdx.x;
    if (tid < E) { s_cnt[tid] = 0; s_cur[tid] = 0; }
    __syncthreads();
    for (int i = tid; i < NSLOT; i += blockDim.x)
        atomicAdd(&s_cnt[sel[i]], 1);
    __syncthreads();
    if (tid == 0) {
        int acc = 0;
        for (int e = 0; e < E; e++) { s_off[e] = acc; acc += s_cnt[e]; }
    }
    __syncthreads();
    if (tid < E) { g_count[tid] = s_cnt[tid]; g_offset[tid] = s_off[tid]; }
    for (int i = tid; i < NSLOT; i += blockDim.x) {
        int e = sel[i];
        int pos = s_off[e] + atomicAdd(&s_cur[e], 1);
        g_tok[pos]   = i / KSEL;
        g_scale[pos] = scales[i];
    }
}

// ---------------- prep: fp32 -> fp16 ---------------------------------------
__global__ void tofp16(const float* __restrict__ src, __half* __restrict__ dst,
                       int n4) {
    int i4 = blockIdx.x * blockDim.x + threadIdx.x;
    if (i4 >= n4) return;
    float4 v = ((const float4*)src)[i4];
    __half2 a = __floats2half2_rn(v.x, v.y);
    __half2 b = __floats2half2_rn(v.z, v.w);
    ((uint2*)dst)[i4] = make_uint2(*(uint32_t*)&a, *(uint32_t*)&b);
}

// ---------------- GEMM1: act = silu(X*W1g+b) * (X*W1l+b) -------------------
// CTA: M=128, Ngate=64, Nlin=64, k-chunk=64, plain fp16.
#define G1_BOFF (128 * ROW_S)              // 18432 (A region size)
#define G1_STG  (G1_BOFF + 128 * ROW_S)    // 36864 per stage

__global__ __launch_bounds__(256, 1)
void gemm1_kernel(const float* __restrict__ b1) {
    const int e   = blockIdx.y;
    const int cnt = g_count[e];
    const int m0  = blockIdx.z * 128;
    if (m0 >= cnt) return;
    const int n0  = blockIdx.x * 64;
    const int off = g_offset[e];

    extern __shared__ char sm[];
    __shared__ float s_bg[64], s_bl[64];

    const int tid = threadIdx.x, lane = tid & 31, wid = tid >> 5;
    const int wm = wid & 1, wn = wid >> 1;

    if (tid < 64)       s_bg[tid]      = b1[(size_t)e * 2 * FF + n0 + tid];
    else if (tid < 128) s_bl[tid - 64] = b1[(size_t)e * 2 * FF + FF + n0 + tid - 64];

    // A staging: 128 rows x 128B; 2 thr/row x 64B (4x uint4)
    const int arow = tid >> 1, ahalf = (tid & 1) * 64;
    const int mrow = m0 + arow;
    const int slot = off + (mrow < cnt ? mrow : cnt - 1);
    const unsigned char* srcA =
        (const unsigned char*)(g_hh + (size_t)g_tok[slot] * H) + ahalf;
    const uint32_t dAo = (uint32_t)arow * ROW_S + ahalf;

    // B staging: 128 rows (64 gate + 64 lin) x 128B; 2 thr/row x 64B
    const int brow = tid >> 1, bhalf = (tid & 1) * 64;
    const int bchan = (brow < 64) ? (e * 2 * FF + n0 + brow)
                                  : (e * 2 * FF + FF + n0 + (brow - 64));
    const unsigned char* srcB =
        (const unsigned char*)(g_w1h + (size_t)bchan * H) + bhalf;
    const uint32_t dBo = G1_BOFF + (uint32_t)brow * ROW_S + bhalf;

    // ldmatrix bases
    const uint32_t smb = s2u(sm);
    const uint32_t laA = (uint32_t)((lane & 15) + wm * 64) * ROW_S + (lane >> 4) * 16;
    // B x4: r0/r1 = j0 k-halves, r2/r3 = j1 k-halves
    const uint32_t lbB = G1_BOFF +
        (uint32_t)(wn * 16 + ((lane >> 4) & 1) * 8 + (lane & 7)) * ROW_S +
        ((lane >> 3) & 1) * 16;

    float cg[4][2][4] = {}, cl[4][2][4] = {};
    uint4 ra[4], rb[4];

#pragma unroll
    for (int q = 0; q < 4; q++) ra[q] = *(const uint4*)(srcA + q * 16);
#pragma unroll
    for (int q = 0; q < 4; q++) rb[q] = *(const uint4*)(srcB + q * 16);

    for (int kt = 0; kt < NK1; kt++) {
        char* bb = sm + (kt & 1) * G1_STG;
#pragma unroll
        for (int q = 0; q < 4; q++) *(uint4*)(bb + dAo + q * 16) = ra[q];
#pragma unroll
        for (int q = 0; q < 4; q++) *(uint4*)(bb + dBo + q * 16) = rb[q];
        __syncthreads();

        if (kt + 1 < NK1) {
            const unsigned char* sa = srcA + (size_t)(kt + 1) * 128;
            const unsigned char* sb = srcB + (size_t)(kt + 1) * 128;
#pragma unroll
            for (int q = 0; q < 4; q++) ra[q] = *(const uint4*)(sa + q * 16);
#pragma unroll
            for (int q = 0; q < 4; q++) rb[q] = *(const uint4*)(sb + q * 16);
        }

        const uint32_t bbu = smb + (kt & 1) * G1_STG;
#pragma unroll
        for (int kk = 0; kk < 4; kk++) {
            uint32_t ah[4][4];
#pragma unroll
            for (int i = 0; i < 4; i++)
                ldsm4(ah[i], bbu + laA + i * (16 * ROW_S) + kk * 32);
            uint32_t bg4[4], bl4[4];
            ldsm4(bg4, bbu + lbB + kk * 32);
            ldsm4(bl4, bbu + lbB + 64 * ROW_S + kk * 32);
#pragma unroll
            for (int i = 0; i < 4; i++) {
                mma16816(cg[i][0], ah[i], &bg4[0]);
                mma16816(cg[i][1], ah[i], &bg4[2]);
                mma16816(cl[i][0], ah[i], &bl4[0]);
                mma16816(cl[i][1], ah[i], &bl4[2]);
            }
        }
        __syncthreads();
    }

    // epilogue: bias + silu(gate)*lin; store act as fp16 pairs
#pragma unroll
    for (int i = 0; i < 4; i++)
#pragma unroll
        for (int rr = 0; rr < 2; rr++) {
            const int m = wm * 64 + i * 16 + (lane >> 2) + rr * 8 + m0;
            if (m >= cnt) continue;
            __half* actrow = g_acth + (size_t)(off + m) * FF;
#pragma unroll
            for (int j = 0; j < 2; j++) {
                const int c = wn * 16 + j * 8 + (lane & 3) * 2;
                float r0, r1;
#pragma unroll
                for (int q = 0; q < 2; q++) {
                    const int idx = rr * 2 + q;
                    const float g = cg[i][j][idx] + s_bg[c + q];
                    const float l = cl[i][j][idx] + s_bl[c + q];
                    const float r = g * l / (1.0f + __expf(-g));
                    if (q == 0) r0 = r; else r1 = r;
                }
                __half2 hv = __floats2half2_rn(r0, r1);
                *(uint32_t*)(actrow + n0 + c) = *(uint32_t*)&hv;
            }
        }
}

// ---------------- GEMM2: out += scale*(act*W2^T + b2) ----------------------
// CTA: M=128, N=64 over H, K=FF, k-chunk=64, plain fp16.
#define G2_BOFF (128 * ROW_S)              // 18432
#define G2_STG  (G2_BOFF + 64 * ROW_S)     // 27648 per stage

__global__ __launch_bounds__(256, 1)
void gemm2_kernel(const float* __restrict__ b2, float* __restrict__ out) {
    const int e   = blockIdx.y;
    const int cnt = g_count[e];
    const int m0  = blockIdx.z * 128;
    if (m0 >= cnt) return;
    const int n0  = blockIdx.x * 64;
    const int off = g_offset[e];

    extern __shared__ char sm[];
    __shared__ float s_b2[64];

    const int tid = threadIdx.x, lane = tid & 31, wid = tid >> 5;
    const int wm = wid & 1, wn = wid >> 1;

    if (tid < 64) s_b2[tid] = b2[(size_t)e * H + n0 + tid];

    // A staging: 128 rows x 128B; 2 thr/row x 64B
    const int arow = tid >> 1, ahalf = (tid & 1) * 64;
    const int mrow = m0 + arow;
    const unsigned char* srcA =
        (const unsigned char*)(g_acth +
            (size_t)(off + (mrow < cnt ? mrow : cnt - 1)) * FF) + ahalf;
    const uint32_t dAo = (uint32_t)arow * ROW_S + ahalf;

    // B staging: 64 rows x 128B; 4 thr/row x 32B (2x uint4)
    const int brow = tid >> 2, bcol = (tid & 3) * 32;
    const unsigned char* srcB =
        (const unsigned char*)(g_w2h + (size_t)(e * H + n0 + brow) * FF) + bcol;
    const uint32_t dBo = G2_BOFF + (uint32_t)brow * ROW_S + bcol;

    const uint32_t smb = s2u(sm);
    const uint32_t laA = (uint32_t)((lane & 15) + wm * 64) * ROW_S + (lane >> 4) * 16;
    const uint32_t lbB = G2_BOFF +
        (uint32_t)(wn * 16 + ((lane >> 4) & 1) * 8 + (lane & 7)) * ROW_S +
        ((lane >> 3) & 1) * 16;

    float c[4][2][4] = {};
    uint4 ra[4], rb[2];

#pragma unroll
    for (int q = 0; q < 4; q++) ra[q] = *(const uint4*)(srcA + q * 16);
#pragma unroll
    for (int q = 0; q < 2; q++) rb[q] = *(const uint4*)(srcB + q * 16);

    for (int kt = 0; kt < NK2; kt++) {
        char* bb = sm + (kt & 1) * G2_STG;
#pragma unroll
        for (int q = 0; q < 4; q++) *(uint4*)(bb + dAo + q * 16) = ra[q];
#pragma unroll
        for (int q = 0; q < 2; q++) *(uint4*)(bb + dBo + q * 16) = rb[q];
        __syncthreads();

        if (kt + 1 < NK2) {
            const unsigned char* sa = srcA + (size_t)(kt + 1) * 128;
            const unsigned char* sb = srcB + (size_t)(kt + 1) * 128;
#pragma unroll
            for (int q = 0; q < 4; q++) ra[q] = *(const uint4*)(sa + q * 16);
#pragma unroll
            for (int q = 0; q < 2; q++) rb[q] = *(const uint4*)(sb + q * 16);
        }

        const uint32_t bbu = smb + (kt & 1) * G2_STG;
#pragma unroll
        for (int kk = 0; kk < 4; kk++) {
            uint32_t ah[4][4];
#pragma unroll
            for (int i = 0; i < 4; i++)
                ldsm4(ah[i], bbu + laA + i * (16 * ROW_S) + kk * 32);
            uint32_t bh4[4];
            ldsm4(bh4, bbu + lbB + kk * 32);
#pragma unroll
            for (int i = 0; i < 4; i++) {
                mma16816(c[i][0], ah[i], &bh4[0]);
                mma16816(c[i][1], ah[i], &bh4[2]);
            }
        }
        __syncthreads();
    }

    // epilogue: scaled atomic scatter
#pragma unroll
    for (int i = 0; i < 4; i++)
#pragma unroll
        for (int rr = 0; rr < 2; rr++) {
            const int m = wm * 64 + i * 16 + (lane >> 2) + rr * 8 + m0;
            if (m >= cnt) continue;
            const int   sl  = off + m;
            const int   tok = g_tok[sl];
            const float sc  = g_scale[sl];
#pragma unroll
            for (int j = 0; j < 2; j++) {
                const int cc = wn * 16 + j * 8 + (lane & 3) * 2;
                atomicAdd(&out[(size_t)tok * H + n0 + cc],
                          sc * (c[i][j][rr * 2 + 0] + s_b2[cc]));
                atomicAdd(&out[(size_t)tok * H + n0 + cc + 1],
                          sc * (c[i][j][rr * 2 + 1] + s_b2[cc + 1]));
            }
        }
}

// ---------------- launch ----------------
extern "C" void kernel_launch(void* const* d_in, const int* in_sizes, int n_in,
                              void* d_out, int out_size) {
    const float* hidden = (const float*)d_in[0];
    const int*   sel    = (const int*)d_in[1];
    const float* scales = (const float*)d_in[2];
    const float* w1     = (const float*)d_in[3];
    const float* b1     = (const float*)d_in[4];
    const float* w2     = (const float*)d_in[5];
    const float* b2     = (const float*)d_in[6];

    void *p_hh, *p_w1h, *p_w2h;
    cudaGetSymbolAddress(&p_hh,  g_hh);
    cudaGetSymbolAddress(&p_w1h, g_w1h);
    cudaGetSymbolAddress(&p_w2h, g_w2h);

    const int smem1 = 2 * G1_STG;   // 73728
    const int smem2 = 2 * G2_STG;   // 55296
    cudaFuncSetAttribute(gemm1_kernel, cudaFuncAttributeMaxDynamicSharedMemorySize, smem1);
    cudaFuncSetAttribute(gemm2_kernel, cudaFuncAttributeMaxDynamicSharedMemorySize, smem2);

    cudaMemsetAsync(d_out, 0, (size_t)T * H * sizeof(float), 0);
    route_kernel<<<1, 256>>>(sel, scales);

    const int n4h  = (T * H) / 4;
    const int n4w1 = (E * 2 * FF * H) / 4;
    const int n4w2 = (E * H * FF) / 4;
    tofp16<<<(n4h  + 255) / 256, 256>>>(hidden, (__half*)p_hh,  n4h);
    tofp16<<<(n4w1 + 255) / 256, 256>>>(w1,     (__half*)p_w1h, n4w1);
    tofp16<<<(n4w2 + 255) / 256, 256>>>(w2,     (__half*)p_w2h, n4w2);

    dim3 g1(FF / 64, E, NSLOT / 128);   // 32 x 8 x 16
    gemm1_kernel<<<g1, 256, smem1>>>(b1);

    dim3 g2(H / 64, E, NSLOT / 128);    // 16 x 8 x 16
    gemm2_kernel<<<g2, 256, smem2>>>(b2, (float*)d_out);
}

// round 10
// speedup vs baseline: 2.5470x; 1.0711x over previous
#include <cuda_runtime.h>
#include <cuda_fp16.h>
#include <math.h>
#include <stdint.h>

#define T 1024
#define H 1024
#define FF 2048
#define E 8
#define KSEL 2
#define NSLOT (T * KSEL)   // 2048
#define NK1 (H / 64)       // 16 k-chunks gemm1
#define NK2 (FF / 64)      // 32 k-chunks gemm2

// ---------------- scratch (device globals: allocation-free) ----------------
__device__ int   g_count[E];
__device__ int   g_offset[E];
__device__ int   g_tok[NSLOT];
__device__ float g_scale[NSLOT];
__device__ __half g_hh[(size_t)T * H];            // 2MB   fp16 hidden
__device__ __half g_acth[(size_t)NSLOT * FF];     // 8MB   fp16 act
__device__ __half g_w1h[(size_t)E * 2 * FF * H];  // 67MB  fp16 w1
__device__ __half g_w2h[(size_t)E * H * FF];      // 33.5MB fp16 w2

// ---------------- helpers ----------------
__device__ __forceinline__ uint32_t s2u(const void* p) {
    return (uint32_t)__cvta_generic_to_shared(p);
}
__device__ __forceinline__ void ldsm4(uint32_t (&r)[4], uint32_t addr) {
    asm volatile("ldmatrix.sync.aligned.m8n8.x4.shared.b16 {%0,%1,%2,%3}, [%4];"
                 : "=r"(r[0]), "=r"(r[1]), "=r"(r[2]), "=r"(r[3]) : "r"(addr));
}
__device__ __forceinline__ void mma16816(float (&c)[4], const uint32_t (&a)[4],
                                         const uint32_t* b) {
    asm volatile(
        "mma.sync.aligned.m16n8k16.row.col.f32.f16.f16.f32 "
        "{%0,%1,%2,%3},{%4,%5,%6,%7},{%8,%9},{%0,%1,%2,%3};"
        : "+f"(c[0]), "+f"(c[1]), "+f"(c[2]), "+f"(c[3])
        : "r"(a[0]), "r"(a[1]), "r"(a[2]), "r"(a[3]), "r"(b[0]), "r"(b[1]));
}

#define ROW_S 144   // 128B data (64 fp16) + 16B pad: conflict-free ldmatrix

// ---------------- routing ----------------
__global__ void route_kernel(const int* __restrict__ sel,
                             const float* __restrict__ scales) {
    __shared__ int s_cnt[E], s_off[E], s_cur[E];
    int tid = threadIdx.x;
    if (tid < E) { s_cnt[tid] = 0; s_cur[tid] = 0; }
    __syncthreads();
    for (int i = tid; i < NSLOT; i += blockDim.x)
        atomicAdd(&s_cnt[sel[i]], 1);
    __syncthreads();
    if (tid == 0) {
        int acc = 0;
        for (int e = 0; e < E; e++) { s_off[e] = acc; acc += s_cnt[e]; }
    }
    __syncthreads();
    if (tid < E) { g_count[tid] = s_cnt[tid]; g_offset[tid] = s_off[tid]; }
    for (int i = tid; i < NSLOT; i += blockDim.x) {
        int e = sel[i];
        int pos = s_off[e] + atomicAdd(&s_cur[e], 1);
        g_tok[pos]   = i / KSEL;
        g_scale[pos] = scales[i];
    }
}

// ---------------- prep: fp32 -> fp16 ---------------------------------------
__global__ void tofp16(const float* __restrict__ src, __half* __restrict__ dst,
                       int n4) {
    int i4 = blockIdx.x * blockDim.x + threadIdx.x;
    if (i4 >= n4) return;
    float4 v = ((const float4*)src)[i4];
    __half2 a = __floats2half2_rn(v.x, v.y);
    __half2 b = __floats2half2_rn(v.z, v.w);
    ((uint2*)dst)[i4] = make_uint2(*(uint32_t*)&a, *(uint32_t*)&b);
}

// ---------------- GEMM1: act = silu(X*W1g+b) * (X*W1l+b) -------------------
// CTA: M=128, Ngate=128, Nlin=128, k-chunk=64, 512 threads (16 warps 4Mx4N).
#define G1_BOFF (128 * ROW_S)              // 18432 (A region)
#define G1_STG  (G1_BOFF + 256 * ROW_S)    // 55296 per stage

__global__ __launch_bounds__(512, 1)
void gemm1_kernel(const float* __restrict__ b1) {
    const int e   = blockIdx.y;
    const int cnt = g_count[e];
    const int m0  = blockIdx.z * 128;
    if (m0 >= cnt) return;
    const int n0  = blockIdx.x * 128;
    const int off = g_offset[e];

    extern __shared__ char sm[];
    __shared__ float s_bg[128], s_bl[128];

    const int tid = threadIdx.x, lane = tid & 31, wid = tid >> 5;
    const int wm = wid & 3, wn = wid >> 2;

    if (tid < 128)      s_bg[tid]       = b1[(size_t)e * 2 * FF + n0 + tid];
    else if (tid < 256) s_bl[tid - 128] = b1[(size_t)e * 2 * FF + FF + n0 + tid - 128];

    // A staging: 128 rows x 128B; 4 thr/row x 32B (2x uint4)
    const int arow = tid >> 2, acol = (tid & 3) * 32;
    const int mrow = m0 + arow;
    const int slot = off + (mrow < cnt ? mrow : cnt - 1);
    const unsigned char* srcA =
        (const unsigned char*)(g_hh + (size_t)g_tok[slot] * H) + acol;
    const uint32_t dAo = (uint32_t)arow * ROW_S + acol;

    // B staging: 256 rows (128 gate + 128 lin) x 128B; 2 thr/row x 64B
    const int brow = tid >> 1, bhalf = (tid & 1) * 64;
    const int bchan = (brow < 128) ? (e * 2 * FF + n0 + brow)
                                   : (e * 2 * FF + FF + n0 + (brow - 128));
    const unsigned char* srcB =
        (const unsigned char*)(g_w1h + (size_t)bchan * H) + bhalf;
    const uint32_t dBo = G1_BOFF + (uint32_t)brow * ROW_S + bhalf;

    // ldmatrix bases
    const uint32_t smb = s2u(sm);
    const uint32_t laA = (uint32_t)((lane & 15) + wm * 32) * ROW_S + (lane >> 4) * 16;
    const uint32_t lbB = G1_BOFF +
        (uint32_t)(wn * 32 + ((lane >> 4) & 1) * 8 + (lane & 7)) * ROW_S +
        ((lane >> 3) & 1) * 16;

    float cg[2][4][4] = {}, cl[2][4][4] = {};
    uint4 ra[2], rb[4];

#pragma unroll
    for (int q = 0; q < 2; q++) ra[q] = *(const uint4*)(srcA + q * 16);
#pragma unroll
    for (int q = 0; q < 4; q++) rb[q] = *(const uint4*)(srcB + q * 16);

    for (int kt = 0; kt < NK1; kt++) {
        char* bb = sm + (kt & 1) * G1_STG;
#pragma unroll
        for (int q = 0; q < 2; q++) *(uint4*)(bb + dAo + q * 16) = ra[q];
#pragma unroll
        for (int q = 0; q < 4; q++) *(uint4*)(bb + dBo + q * 16) = rb[q];
        __syncthreads();

        if (kt + 1 < NK1) {
            const unsigned char* sa = srcA + (size_t)(kt + 1) * 128;
            const unsigned char* sb = srcB + (size_t)(kt + 1) * 128;
#pragma unroll
            for (int q = 0; q < 2; q++) ra[q] = *(const uint4*)(sa + q * 16);
#pragma unroll
            for (int q = 0; q < 4; q++) rb[q] = *(const uint4*)(sb + q * 16);
        }

        const uint32_t bbu = smb + (kt & 1) * G1_STG;
#pragma unroll
        for (int kk = 0; kk < 4; kk++) {
            uint32_t ah[2][4];
#pragma unroll
            for (int i = 0; i < 2; i++)
                ldsm4(ah[i], bbu + laA + i * (16 * ROW_S) + kk * 32);
            uint32_t bgA[4], bgB[4], blA[4], blB[4];
            ldsm4(bgA, bbu + lbB + kk * 32);
            ldsm4(bgB, bbu + lbB + 16 * ROW_S + kk * 32);
            ldsm4(blA, bbu + lbB + 128 * ROW_S + kk * 32);
            ldsm4(blB, bbu + lbB + 144 * ROW_S + kk * 32);
#pragma unroll
            for (int i = 0; i < 2; i++) {
                mma16816(cg[i][0], ah[i], &bgA[0]);
                mma16816(cg[i][1], ah[i], &bgA[2]);
                mma16816(cg[i][2], ah[i], &bgB[0]);
                mma16816(cg[i][3], ah[i], &bgB[2]);
                mma16816(cl[i][0], ah[i], &blA[0]);
                mma16816(cl[i][1], ah[i], &blA[2]);
                mma16816(cl[i][2], ah[i], &blB[0]);
                mma16816(cl[i][3], ah[i], &blB[2]);
            }
        }
        __syncthreads();
    }

    // epilogue: bias + silu(gate)*lin; store act as fp16 pairs
#pragma unroll
    for (int i = 0; i < 2; i++)
#pragma unroll
        for (int rr = 0; rr < 2; rr++) {
            const int m = wm * 32 + i * 16 + (lane >> 2) + rr * 8 + m0;
            if (m >= cnt) continue;
            __half* actrow = g_acth + (size_t)(off + m) * FF;
#pragma unroll
            for (int j = 0; j < 4; j++) {
                const int c = wn * 32 + j * 8 + (lane & 3) * 2;
                float r0, r1;
#pragma unroll
                for (int q = 0; q < 2; q++) {
                    const int idx = rr * 2 + q;
                    const float g = cg[i][j][idx] + s_bg[c + q];
                    const float l = cl[i][j][idx] + s_bl[c + q];
                    const float r = g * l / (1.0f + __expf(-g));
                    if (q == 0) r0 = r; else r1 = r;
                }
                __half2 hv = __floats2half2_rn(r0, r1);
                *(uint32_t*)(actrow + n0 + c) = *(uint32_t*)&hv;
            }
        }
}

// ---------------- GEMM2: out += scale*(act*W2^T + b2) ----------------------
// CTA: M=128, N=128 over H, k-chunk=64, 512 threads.
#define G2_BOFF (128 * ROW_S)              // 18432
#define G2_STG  (G2_BOFF + 128 * ROW_S)    // 36864 per stage

__global__ __launch_bounds__(512, 1)
void gemm2_kernel(const float* __restrict__ b2, float* __restrict__ out) {
    const int e   = blockIdx.y;
    const int cnt = g_count[e];
    const int m0  = blockIdx.z * 128;
    if (m0 >= cnt) return;
    const int n0  = blockIdx.x * 128;
    const int off = g_offset[e];

    extern __shared__ char sm[];
    __shared__ float s_b2[128];

    const int tid = threadIdx.x, lane = tid & 31, wid = tid >> 5;
    const int wm = wid & 3, wn = wid >> 2;

    if (tid < 128) s_b2[tid] = b2[(size_t)e * H + n0 + tid];

    // A staging: 128 rows x 128B; 4 thr/row x 32B
    const int arow = tid >> 2, acol = (tid & 3) * 32;
    const int mrow = m0 + arow;
    const unsigned char* srcA =
        (const unsigned char*)(g_acth +
            (size_t)(off + (mrow < cnt ? mrow : cnt - 1)) * FF) + acol;
    const uint32_t dAo = (uint32_t)arow * ROW_S + acol;

    // B staging: 128 rows x 128B; 4 thr/row x 32B
    const int brow = tid >> 2, bcol = (tid & 3) * 32;
    const unsigned char* srcB =
        (const unsigned char*)(g_w2h + (size_t)(e * H + n0 + brow) * FF) + bcol;
    const uint32_t dBo = G2_BOFF + (uint32_t)brow * ROW_S + bcol;

    const uint32_t smb = s2u(sm);
    const uint32_t laA = (uint32_t)((lane & 15) + wm * 32) * ROW_S + (lane >> 4) * 16;
    const uint32_t lbB = G2_BOFF +
        (uint32_t)(wn * 32 + ((lane >> 4) & 1) * 8 + (lane & 7)) * ROW_S +
        ((lane >> 3) & 1) * 16;

    float c[2][4][4] = {};
    uint4 ra[2], rb[2];

#pragma unroll
    for (int q = 0; q < 2; q++) ra[q] = *(const uint4*)(srcA + q * 16);
#pragma unroll
    for (int q = 0; q < 2; q++) rb[q] = *(const uint4*)(srcB + q * 16);

    for (int kt = 0; kt < NK2; kt++) {
        char* bb = sm + (kt & 1) * G2_STG;
#pragma unroll
        for (int q = 0; q < 2; q++) *(uint4*)(bb + dAo + q * 16) = ra[q];
#pragma unroll
        for (int q = 0; q < 2; q++) *(uint4*)(bb + dBo + q * 16) = rb[q];
        __syncthreads();

        if (kt + 1 < NK2) {
            const unsigned char* sa = srcA + (size_t)(kt + 1) * 128;
            const unsigned char* sb = srcB + (size_t)(kt + 1) * 128;
#pragma unroll
            for (int q = 0; q < 2; q++) ra[q] = *(const uint4*)(sa + q * 16);
#pragma unroll
            for (int q = 0; q < 2; q++) rb[q] = *(const uint4*)(sb + q * 16);
        }

        const uint32_t bbu = smb + (kt & 1) * G2_STG;
#pragma unroll
        for (int kk = 0; kk < 4; kk++) {
            uint32_t ah[2][4];
#pragma unroll
            for (int i = 0; i < 2; i++)
                ldsm4(ah[i], bbu + laA + i * (16 * ROW_S) + kk * 32);
            uint32_t bhA[4], bhB[4];
            ldsm4(bhA, bbu + lbB + kk * 32);
            ldsm4(bhB, bbu + lbB + 16 * ROW_S + kk * 32);
#pragma unroll
            for (int i = 0; i < 2; i++) {
                mma16816(c[i][0], ah[i], &bhA[0]);
                mma16816(c[i][1], ah[i], &bhA[2]);
                mma16816(c[i][2], ah[i], &bhB[0]);
                mma16816(c[i][3], ah[i], &bhB[2]);
            }
        }
        __syncthreads();
    }

    // epilogue: scaled atomic scatter
#pragma unroll
    for (int i = 0; i < 2; i++)
#pragma unroll
        for (int rr = 0; rr < 2; rr++) {
            const int m = wm * 32 + i * 16 + (lane >> 2) + rr * 8 + m0;
            if (m >= cnt) continue;
            const int   sl  = off + m;
            const int   tok = g_tok[sl];
            const float sc  = g_scale[sl];
#pragma unroll
            for (int j = 0; j < 4; j++) {
                const int cc = wn * 32 + j * 8 + (lane & 3) * 2;
                atomicAdd(&out[(size_t)tok * H + n0 + cc],
                          sc * (c[i][j][rr * 2 + 0] + s_b2[cc]));
                atomicAdd(&out[(size_t)tok * H + n0 + cc + 1],
                          sc * (c[i][j][rr * 2 + 1] + s_b2[cc + 1]));
            }
        }
}

// ---------------- launch ----------------
extern "C" void kernel_launch(void* const* d_in, const int* in_sizes, int n_in,
                              void* d_out, int out_size) {
    const float* hidden = (const float*)d_in[0];
    const int*   sel    = (const int*)d_in[1];
    const float* scales = (const float*)d_in[2];
    const float* w1     = (const float*)d_in[3];
    const float* b1     = (const float*)d_in[4];
    const float* w2     = (const float*)d_in[5];
    const float* b2     = (const float*)d_in[6];

    void *p_hh, *p_w1h, *p_w2h;
    cudaGetSymbolAddress(&p_hh,  g_hh);
    cudaGetSymbolAddress(&p_w1h, g_w1h);
    cudaGetSymbolAddress(&p_w2h, g_w2h);

    const int smem1 = 2 * G1_STG;   // 110592
    const int smem2 = 2 * G2_STG;   // 73728
    cudaFuncSetAttribute(gemm1_kernel, cudaFuncAttributeMaxDynamicSharedMemorySize, smem1);
    cudaFuncSetAttribute(gemm2_kernel, cudaFuncAttributeMaxDynamicSharedMemorySize, smem2);

    cudaMemsetAsync(d_out, 0, (size_t)T * H * sizeof(float), 0);
    route_kernel<<<1, 256>>>(sel, scales);

    const int n4h  = (T * H) / 4;
    const int n4w1 = (E * 2 * FF * H) / 4;
    const int n4w2 = (E * H * FF) / 4;
    tofp16<<<(n4h  + 255) / 256, 256>>>(hidden, (__half*)p_hh,  n4h);
    tofp16<<<(n4w1 + 255) / 256, 256>>>(w1,     (__half*)p_w1h, n4w1);
    tofp16<<<(n4w2 + 255) / 256, 256>>>(w2,     (__half*)p_w2h, n4w2);

    dim3 g1(FF / 128, E, NSLOT / 128);   // 16 x 8 x 16
    gemm1_kernel<<<g1, 512, smem1>>>(b1);

    dim3 g2(H / 128, E, NSLOT / 128);    // 8 x 8 x 16
    gemm2_kernel<<<g2, 512, smem2>>>(b2, (float*)d_out);
}

// round 11
// speedup vs baseline: 2.7681x; 1.0868x over previous
#include <cuda_runtime.h>
#include <cuda_fp16.h>
#include <math.h>
#include <stdint.h>

#define T 1024
#define H 1024
#define FF 2048
#define E 8
#define KSEL 2
#define NSLOT (T * KSEL)   // 2048
#define NK1 (H / 64)       // 16 k-chunks gemm1
#define NK2 (FF / 64)      // 32 k-chunks gemm2

// ---------------- scratch (device globals: allocation-free) ----------------
__device__ int   g_count[E];
__device__ int   g_offset[E];
__device__ int   g_tok[NSLOT];
__device__ float g_scale[NSLOT];
__device__ __half g_hh[(size_t)T * H];            // 2MB   fp16 hidden
__device__ __half g_acth[(size_t)NSLOT * FF];     // 8MB   fp16 act
__device__ __half g_w1h[(size_t)E * 2 * FF * H];  // 67MB  fp16 w1
__device__ __half g_w2h[(size_t)E * H * FF];      // 33.5MB fp16 w2

// ---------------- helpers ----------------
__device__ __forceinline__ uint32_t s2u(const void* p) {
    return (uint32_t)__cvta_generic_to_shared(p);
}
__device__ __forceinline__ void ldsm4(uint32_t (&r)[4], uint32_t addr) {
    asm volatile("ldmatrix.sync.aligned.m8n8.x4.shared.b16 {%0,%1,%2,%3}, [%4];"
                 : "=r"(r[0]), "=r"(r[1]), "=r"(r[2]), "=r"(r[3]) : "r"(addr));
}
__device__ __forceinline__ void mma16816(float (&c)[4], const uint32_t (&a)[4],
                                         const uint32_t* b) {
    asm volatile(
        "mma.sync.aligned.m16n8k16.row.col.f32.f16.f16.f32 "
        "{%0,%1,%2,%3},{%4,%5,%6,%7},{%8,%9},{%0,%1,%2,%3};"
        : "+f"(c[0]), "+f"(c[1]), "+f"(c[2]), "+f"(c[3])
        : "r"(a[0]), "r"(a[1]), "r"(a[2]), "r"(a[3]), "r"(b[0]), "r"(b[1]));
}

#define ROW_S 144   // 128B data (64 fp16) + 16B pad: conflict-free ldmatrix

// ---------------- routing ----------------
__global__ void route_kernel(const int* __restrict__ sel,
                             const float* __restrict__ scales) {
    __shared__ int s_cnt[E], s_off[E], s_cur[E];
    int tid = threadIdx.x;
    if (tid < E) { s_cnt[tid] = 0; s_cur[tid] = 0; }
    __syncthreads();
    for (int i = tid; i < NSLOT; i += blockDim.x)
        atomicAdd(&s_cnt[sel[i]], 1);
    __syncthreads();
    if (tid == 0) {
        int acc = 0;
        for (int e = 0; e < E; e++) { s_off[e] = acc; acc += s_cnt[e]; }
    }
    __syncthreads();
    if (tid < E) { g_count[tid] = s_cnt[tid]; g_offset[tid] = s_off[tid]; }
    for (int i = tid; i < NSLOT; i += blockDim.x) {
        int e = sel[i];
        int pos = s_off[e] + atomicAdd(&s_cur[e], 1);
        g_tok[pos]   = i / KSEL;
        g_scale[pos] = scales[i];
    }
}

// ---------------- prep: all three fp32 -> fp16 conversions, one launch -----
#define N4H  (T * H / 4)
#define N4W1 (E * 2 * FF * H / 4)
#define N4W2 (E * H * FF / 4)

__global__ void prep_all(const float* __restrict__ hidden,
                         const float* __restrict__ w1,
                         const float* __restrict__ w2,
                         __half* __restrict__ dh,
                         __half* __restrict__ dw1,
                         __half* __restrict__ dw2) {
    int i4 = blockIdx.x * blockDim.x + threadIdx.x;
    const float* src;
    __half* dst;
    if (i4 < N4W1)                 { src = w1; dst = dw1; }
    else if (i4 < N4W1 + N4W2)     { i4 -= N4W1; src = w2; dst = dw2; }
    else if (i4 < N4W1 + N4W2 + N4H) { i4 -= N4W1 + N4W2; src = hidden; dst = dh; }
    else return;
    float4 v = ((const float4*)src)[i4];
    __half2 a = __floats2half2_rn(v.x, v.y);
    __half2 b = __floats2half2_rn(v.z, v.w);
    ((uint2*)dst)[i4] = make_uint2(*(uint32_t*)&a, *(uint32_t*)&b);
}

// ---------------- GEMM1: act = silu(X*W1g+b) * (X*W1l+b) -------------------
// CTA: M=128, Ngate=128, Nlin=128, k-chunk=64, 512 threads (16 warps 4Mx4N).
// Single sync per k-iter; LDG overlapped with barrier wait.
#define G1_BOFF (128 * ROW_S)              // 18432 (A region)
#define G1_STG  (G1_BOFF + 256 * ROW_S)    // 55296 per stage

__global__ __launch_bounds__(512, 1)
void gemm1_kernel(const float* __restrict__ b1) {
    const int e   = blockIdx.y;
    const int cnt = g_count[e];
    const int m0  = blockIdx.z * 128;
    if (m0 >= cnt) return;
    const int n0  = blockIdx.x * 128;
    const int off = g_offset[e];

    extern __shared__ char sm[];
    __shared__ float s_bg[128], s_bl[128];

    const int tid = threadIdx.x, lane = tid & 31, wid = tid >> 5;
    const int wm = wid & 3, wn = wid >> 2;

    if (tid < 128)      s_bg[tid]       = b1[(size_t)e * 2 * FF + n0 + tid];
    else if (tid < 256) s_bl[tid - 128] = b1[(size_t)e * 2 * FF + FF + n0 + tid - 128];

    // A staging: 128 rows x 128B; 4 thr/row x 32B (2x uint4)
    const int arow = tid >> 2, acol = (tid & 3) * 32;
    const int mrow = m0 + arow;
    const int slot = off + (mrow < cnt ? mrow : cnt - 1);
    const unsigned char* srcA =
        (const unsigned char*)(g_hh + (size_t)g_tok[slot] * H) + acol;
    const uint32_t dAo = (uint32_t)arow * ROW_S + acol;

    // B staging: 256 rows (128 gate + 128 lin) x 128B; 2 thr/row x 64B
    const int brow = tid >> 1, bhalf = (tid & 1) * 64;
    const int bchan = (brow < 128) ? (e * 2 * FF + n0 + brow)
                                   : (e * 2 * FF + FF + n0 + (brow - 128));
    const unsigned char* srcB =
        (const unsigned char*)(g_w1h + (size_t)bchan * H) + bhalf;
    const uint32_t dBo = G1_BOFF + (uint32_t)brow * ROW_S + bhalf;

    // ldmatrix bases
    const uint32_t smb = s2u(sm);
    const uint32_t laA = (uint32_t)((lane & 15) + wm * 32) * ROW_S + (lane >> 4) * 16;
    const uint32_t lbB = G1_BOFF +
        (uint32_t)(wn * 32 + ((lane >> 4) & 1) * 8 + (lane & 7)) * ROW_S +
        ((lane >> 3) & 1) * 16;

    float cg[2][4][4] = {}, cl[2][4][4] = {};
    uint4 ra[2], rb[4];

#pragma unroll
    for (int q = 0; q < 2; q++) ra[q] = *(const uint4*)(srcA + q * 16);
#pragma unroll
    for (int q = 0; q < 4; q++) rb[q] = *(const uint4*)(srcB + q * 16);

    for (int kt = 0; kt < NK1; kt++) {
        char* bb = sm + (kt & 1) * G1_STG;
#pragma unroll
        for (int q = 0; q < 2; q++) *(uint4*)(bb + dAo + q * 16) = ra[q];
#pragma unroll
        for (int q = 0; q < 4; q++) *(uint4*)(bb + dBo + q * 16) = rb[q];

        if (kt + 1 < NK1) {
            const unsigned char* sa = srcA + (size_t)(kt + 1) * 128;
            const unsigned char* sb = srcB + (size_t)(kt + 1) * 128;
#pragma unroll
            for (int q = 0; q < 2; q++) ra[q] = *(const uint4*)(sa + q * 16);
#pragma unroll
            for (int q = 0; q < 4; q++) rb[q] = *(const uint4*)(sb + q * 16);
        }
        __syncthreads();

        const uint32_t bbu = smb + (kt & 1) * G1_STG;
#pragma unroll
        for (int kk = 0; kk < 4; kk++) {
            uint32_t ah[2][4];
#pragma unroll
            for (int i = 0; i < 2; i++)
                ldsm4(ah[i], bbu + laA + i * (16 * ROW_S) + kk * 32);
            uint32_t bgA[4], bgB[4], blA[4], blB[4];
            ldsm4(bgA, bbu + lbB + kk * 32);
            ldsm4(bgB, bbu + lbB + 16 * ROW_S + kk * 32);
            ldsm4(blA, bbu + lbB + 128 * ROW_S + kk * 32);
            ldsm4(blB, bbu + lbB + 144 * ROW_S + kk * 32);
#pragma unroll
            for (int i = 0; i < 2; i++) {
                mma16816(cg[i][0], ah[i], &bgA[0]);
                mma16816(cg[i][1], ah[i], &bgA[2]);
                mma16816(cg[i][2], ah[i], &bgB[0]);
                mma16816(cg[i][3], ah[i], &bgB[2]);
                mma16816(cl[i][0], ah[i], &blA[0]);
                mma16816(cl[i][1], ah[i], &blA[2]);
                mma16816(cl[i][2], ah[i], &blB[0]);
                mma16816(cl[i][3], ah[i], &blB[2]);
            }
        }
    }

    // epilogue: bias + silu(gate)*lin; store act as fp16 pairs
#pragma unroll
    for (int i = 0; i < 2; i++)
#pragma unroll
        for (int rr = 0; rr < 2; rr++) {
            const int m = wm * 32 + i * 16 + (lane >> 2) + rr * 8 + m0;
            if (m >= cnt) continue;
            __half* actrow = g_acth + (size_t)(off + m) * FF;
#pragma unroll
            for (int j = 0; j < 4; j++) {
                const int c = wn * 32 + j * 8 + (lane & 3) * 2;
                float r0, r1;
#pragma unroll
                for (int q = 0; q < 2; q++) {
                    const int idx = rr * 2 + q;
                    const float g = cg[i][j][idx] + s_bg[c + q];
                    const float l = cl[i][j][idx] + s_bl[c + q];
                    const float r = g * l / (1.0f + __expf(-g));
                    if (q == 0) r0 = r; else r1 = r;
                }
                __half2 hv = __floats2half2_rn(r0, r1);
                *(uint32_t*)(actrow + n0 + c) = *(uint32_t*)&hv;
            }
        }
}

// ---------------- GEMM2: out += scale*(act*W2^T + b2) ----------------------
// CTA: M=128, N=128 over H, k-chunk=64, 512 threads. Single sync/iter.
#define G2_BOFF (128 * ROW_S)              // 18432
#define G2_STG  (G2_BOFF + 128 * ROW_S)    // 36864 per stage

__global__ __launch_bounds__(512, 1)
void gemm2_kernel(const float* __restrict__ b2, float* __restrict__ out) {
    const int e   = blockIdx.y;
    const int cnt = g_count[e];
    const int m0  = blockIdx.z * 128;
    if (m0 >= cnt) return;
    const int n0  = blockIdx.x * 128;
    const int off = g_offset[e];

    extern __shared__ char sm[];
    __shared__ float s_b2[128];

    const int tid = threadIdx.x, lane = tid & 31, wid = tid >> 5;
    const int wm = wid & 3, wn = wid >> 2;

    if (tid < 128) s_b2[tid] = b2[(size_t)e * H + n0 + tid];

    // A staging: 128 rows x 128B; 4 thr/row x 32B
    const int arow = tid >> 2, acol = (tid & 3) * 32;
    const int mrow = m0 + arow;
    const unsigned char* srcA =
        (const unsigned char*)(g_acth +
            (size_t)(off + (mrow < cnt ? mrow : cnt - 1)) * FF) + acol;
    const uint32_t dAo = (uint32_t)arow * ROW_S + acol;

    // B staging: 128 rows x 128B; 4 thr/row x 32B
    const int brow = tid >> 2, bcol = (tid & 3) * 32;
    const unsigned char* srcB =
        (const unsigned char*)(g_w2h + (size_t)(e * H + n0 + brow) * FF) + bcol;
    const uint32_t dBo = G2_BOFF + (uint32_t)brow * ROW_S + bcol;

    const uint32_t smb = s2u(sm);
    const uint32_t laA = (uint32_t)((lane & 15) + wm * 32) * ROW_S + (lane >> 4) * 16;
    const uint32_t lbB = G2_BOFF +
        (uint32_t)(wn * 32 + ((lane >> 4) & 1) * 8 + (lane & 7)) * ROW_S +
        ((lane >> 3) & 1) * 16;

    float c[2][4][4] = {};
    uint4 ra[2], rb[2];

#pragma unroll
    for (int q = 0; q < 2; q++) ra[q] = *(const uint4*)(srcA + q * 16);
#pragma unroll
    for (int q = 0; q < 2; q++) rb[q] = *(const uint4*)(srcB + q * 16);

    for (int kt = 0; kt < NK2; kt++) {
        char* bb = sm + (kt & 1) * G2_STG;
#pragma unroll
        for (int q = 0; q < 2; q++) *(uint4*)(bb + dAo + q * 16) = ra[q];
#pragma unroll
        for (int q = 0; q < 2; q++) *(uint4*)(bb + dBo + q * 16) = rb[q];

        if (kt + 1 < NK2) {
            const unsigned char* sa = srcA + (size_t)(kt + 1) * 128;
            const unsigned char* sb = srcB + (size_t)(kt + 1) * 128;
#pragma unroll
            for (int q = 0; q < 2; q++) ra[q] = *(const uint4*)(sa + q * 16);
#pragma unroll
            for (int q = 0; q < 2; q++) rb[q] = *(const uint4*)(sb + q * 16);
        }
        __syncthreads();

        const uint32_t bbu = smb + (kt & 1) * G2_STG;
#pragma unroll
        for (int kk = 0; kk < 4; kk++) {
            uint32_t ah[2][4];
#pragma unroll
            for (int i = 0; i < 2; i++)
                ldsm4(ah[i], bbu + laA + i * (16 * ROW_S) + kk * 32);
            uint32_t bhA[4], bhB[4];
            ldsm4(bhA, bbu + lbB + kk * 32);
            ldsm4(bhB, bbu + lbB + 16 * ROW_S + kk * 32);
#pragma unroll
            for (int i = 0; i < 2; i++) {
                mma16816(c[i][0], ah[i], &bhA[0]);
                mma16816(c[i][1], ah[i], &bhA[2]);
                mma16816(c[i][2], ah[i], &bhB[0]);
                mma16816(c[i][3], ah[i], &bhB[2]);
            }
        }
    }

    // epilogue: scaled atomic scatter
#pragma unroll
    for (int i = 0; i < 2; i++)
#pragma unroll
        for (int rr = 0; rr < 2; rr++) {
            const int m = wm * 32 + i * 16 + (lane >> 2) + rr * 8 + m0;
            if (m >= cnt) continue;
            const int   sl  = off + m;
            const int   tok = g_tok[sl];
            const float sc  = g_scale[sl];
#pragma unroll
            for (int j = 0; j < 4; j++) {
                const int cc = wn * 32 + j * 8 + (lane & 3) * 2;
                atomicAdd(&out[(size_t)tok * H + n0 + cc],
                          sc * (c[i][j][rr * 2 + 0] + s_b2[cc]));
                atomicAdd(&out[(size_t)tok * H + n0 + cc + 1],
                          sc * (c[i][j][rr * 2 + 1] + s_b2[cc + 1]));
            }
        }
}

// ---------------- launch ----------------
extern "C" void kernel_launch(void* const* d_in, const int* in_sizes, int n_in,
                              void* d_out, int out_size) {
    const float* hidden = (const float*)d_in[0];
    const int*   sel    = (const int*)d_in[1];
    const float* scales = (const float*)d_in[2];
    const float* w1     = (const float*)d_in[3];
    const float* b1     = (const float*)d_in[4];
    const float* w2     = (const float*)d_in[5];
    const float* b2     = (const float*)d_in[6];

    void *p_hh, *p_w1h, *p_w2h;
    cudaGetSymbolAddress(&p_hh,  g_hh);
    cudaGetSymbolAddress(&p_w1h, g_w1h);
    cudaGetSymbolAddress(&p_w2h, g_w2h);

    const int smem1 = 2 * G1_STG;   // 110592
    const int smem2 = 2 * G2_STG;   // 73728
    cudaFuncSetAttribute(gemm1_kernel, cudaFuncAttributeMaxDynamicSharedMemorySize, smem1);
    cudaFuncSetAttribute(gemm2_kernel, cudaFuncAttributeMaxDynamicSharedMemorySize, smem2);

    cudaMemsetAsync(d_out, 0, (size_t)T * H * sizeof(float), 0);
    route_kernel<<<1, 256>>>(sel, scales);

    const int n4all = N4H + N4W1 + N4W2;
    prep_all<<<(n4all + 255) / 256, 256>>>(hidden, w1, w2,
                                           (__half*)p_hh, (__half*)p_w1h,
                                           (__half*)p_w2h);

    dim3 g1(FF / 128, E, NSLOT / 128);   // 16 x 8 x 16
    gemm1_kernel<<<g1, 512, smem1>>>(b1);

    dim3 g2(H / 128, E, NSLOT / 128);    // 8 x 8 x 16
    gemm2_kernel<<<g2, 512, smem2>>>(b2, (float*)d_out);
}